// round 10
// baseline (speedup 1.0000x reference)
#include <cuda_runtime.h>
#include <cuda_bf16.h>
#include <math.h>

// Problem constants
#define B 16
#define NN 50
#define H 128
#define V 40000
#define STEPS 2
#define VM1 39999   // output vocab (emb[1:])

typedef unsigned long long u64;

// packed 2x fp32 FMA (Blackwell f32x2: 2 MACs per issue slot, rt=2 like FFMA)
__device__ __forceinline__ void ffma2(u64& d, u64 a, u64 b) {
    asm("fma.rn.f32x2 %0, %1, %2, %0;" : "+l"(d) : "l"(a), "l"(b));
}
__device__ __forceinline__ u64 pack2(float lo, float hi) {
    u64 r; asm("mov.b64 %0, {%1, %2};" : "=l"(r) : "f"(lo), "f"(hi)); return r;
}
__device__ __forceinline__ void unpack2(u64 p, float& lo, float& hi) {
    asm("mov.b64 {%0, %1}, %2;" : "=f"(lo), "=f"(hi) : "l"(p));
}
__device__ __forceinline__ float hsum2(u64 p) {
    float lo, hi; unpack2(p, lo, hi); return lo + hi;
}

// ---------------- scratch (no allocation allowed) ----------------
__device__ __align__(16) float g_hidden[B*NN*H];
__device__ __align__(16) float g_ein[B*NN*H];
__device__ __align__(16) float g_eout[B*NN*H];
__device__ __align__(16) float g_inputs[B*NN*2*H];
__device__ __align__(16) float g_gi[B*NN*3*H];
__device__ __align__(16) float g_gh[B*NN*3*H];
__device__ __align__(16) float g_q2[B*NN*H];
__device__ __align__(16) float g_qt[B*NN*H];
__device__ __align__(16) float g_avec[B*H];
__device__ int g_len[B];

// ---------------- kernels ----------------

// hidden[r][h] = emb[items[r]][h]
__global__ void k_embed(const int* __restrict__ items, const float* __restrict__ emb,
                        float* __restrict__ hidden) {
    int r = blockIdx.x, h = threadIdx.x;
    hidden[r*H + h] = emb[items[r]*H + h];
}

// Shared GEMM body: C[M x N] = X[M x K] @ W[N x K]^T + bias
// (tiled 64x64, 256 threads, 4x4 microtile). Optional row mask applied to X.
// Register-prefetch double buffering: LDG for chunk k+1 overlaps inner compute on k.
__device__ __forceinline__ void gemm_body(const float* __restrict__ X, const float* __restrict__ W,
                                          const float* __restrict__ bias, float* __restrict__ C,
                                          int M, int N, int K, const int* __restrict__ mask) {
    __shared__ float Xs[64][17];
    __shared__ float Ws[64][17];
    const int i0 = blockIdx.y * 64;
    const int j0 = blockIdx.x * 64;
    const int tx = threadIdx.x & 15;      // col group
    const int ty = threadIdx.x >> 4;      // row group
    float acc[4][4];
#pragma unroll
    for (int a = 0; a < 4; a++)
#pragma unroll
        for (int b = 0; b < 4; b++) acc[a][b] = 0.f;

    float rx[4], rw[4];
#pragma unroll
    for (int l = 0; l < 4; l++) {
        int idx = l*256 + threadIdx.x;
        int i = idx >> 4, k = idx & 15;
        int gi = i0 + i;
        float xv = 0.f;
        if (gi < M) { xv = X[gi*K + k]; if (mask && !mask[gi]) xv = 0.f; }
        rx[l] = xv;
        int gj = j0 + i;
        rw[l] = (gj < N) ? W[gj*K + k] : 0.f;
    }

    for (int k0 = 0; k0 < K; k0 += 16) {
#pragma unroll
        for (int l = 0; l < 4; l++) {
            int idx = l*256 + threadIdx.x;
            int i = idx >> 4, k = idx & 15;
            Xs[i][k] = rx[l];
            Ws[i][k] = rw[l];
        }
        __syncthreads();
        if (k0 + 16 < K) {
#pragma unroll
            for (int l = 0; l < 4; l++) {
                int idx = l*256 + threadIdx.x;
                int i = idx >> 4, k = idx & 15;
                int gi = i0 + i;
                float xv = 0.f;
                if (gi < M) { xv = X[gi*K + k0 + 16 + k]; if (mask && !mask[gi]) xv = 0.f; }
                rx[l] = xv;
                int gj = j0 + i;
                rw[l] = (gj < N) ? W[gj*K + k0 + 16 + k] : 0.f;
            }
        }
#pragma unroll
        for (int k = 0; k < 16; k++) {
            float xr[4], wr[4];
#pragma unroll
            for (int a = 0; a < 4; a++) { xr[a] = Xs[ty*4+a][k]; wr[a] = Ws[tx*4+a][k]; }
#pragma unroll
            for (int a = 0; a < 4; a++)
#pragma unroll
                for (int b = 0; b < 4; b++) acc[a][b] += xr[a] * wr[b];
        }
        __syncthreads();
    }
#pragma unroll
    for (int a = 0; a < 4; a++) {
        int i = i0 + ty*4 + a;
        if (i >= M) continue;
#pragma unroll
        for (int b = 0; b < 4; b++) {
            int j = j0 + tx*4 + b;
            float v = acc[a][b];
            if (bias) v += bias[j];
            C[i*N + j] = v;
        }
    }
}

// fused ein/eout GEMMs (blockIdx.z selects)
__global__ void k_einout(const float* hidden, const float* W_ein, const float* b_ein, float* ein,
                         const float* W_eout, const float* b_eout, float* eout) {
    if (blockIdx.z == 0) gemm_body(hidden, W_ein,  b_ein,  ein,  B*NN, H, H, nullptr);
    else                 gemm_body(hidden, W_eout, b_eout, eout, B*NN, H, H, nullptr);
}

// fused gate GEMMs
__global__ void k_gates(const float* inputs, const float* hidden,
                        const float* w_ih, const float* b_ih, float* gi_,
                        const float* w_hh, const float* b_hh, float* gh_) {
    if (blockIdx.z == 0) gemm_body(inputs, w_ih, b_ih, gi_, B*NN, 3*H, 2*H, nullptr);
    else                 gemm_body(hidden, w_hh, b_hh, gh_, B*NN, 3*H, H,   nullptr);
}

// fused q2/qt GEMMs
__global__ void k_q2qt(const float* hidden, const float* W_two, const float* b_two, float* q2,
                       const float* W_t, float* qt, const int* mask) {
    if (blockIdx.z == 0) gemm_body(hidden, W_two, b_two,   q2, B*NN, H, H, nullptr);
    else                 gemm_body(hidden, W_t,   nullptr, qt, B*NN, H, H, mask);
}

// inputs[r] = [A_in[r] @ ein_b + b_iah , A_out[r] @ eout_b + b_oah]
__global__ void k_Amul(const float* __restrict__ A, const float* __restrict__ ein,
                       const float* __restrict__ eout, const float* __restrict__ b_iah,
                       const float* __restrict__ b_oah, float* __restrict__ inputs) {
    int r = blockIdx.x, b = r / NN;
    int tid = threadIdx.x;
    int half = tid >> 7, h = tid & 127;
    __shared__ float Ar[2*NN];
    __shared__ float red[2*H];
    if (tid < 2*NN) Ar[tid] = A[r*2*NN + tid];
    __syncthreads();
    const float* eb = ein  + b*NN*H + h;
    const float* ob = eout + b*NN*H + h;
    float ain = 0.f, aout = 0.f;
    int m0 = half * 25;
#pragma unroll
    for (int m = 0; m < 25; m++) {
        ain  += Ar[m0 + m]      * eb[(m0 + m)*H];
        aout += Ar[NN + m0 + m] * ob[(m0 + m)*H];
    }
    if (half) { red[h] = ain; red[H + h] = aout; }
    __syncthreads();
    if (!half) {
        inputs[r*2*H + h]     = ain  + red[h]     + b_iah[h];
        inputs[r*2*H + H + h] = aout + red[H + h] + b_oah[h];
    }
}

// GRU gate update (in-place on hidden)
__global__ void k_gru(const float* __restrict__ gi, const float* __restrict__ gh,
                      float* __restrict__ hidden) {
    int r = blockIdx.x, h = threadIdx.x;
    float i_r = gi[r*3*H + h], i_i = gi[r*3*H + H + h], i_n = gi[r*3*H + 2*H + h];
    float h_r = gh[r*3*H + h], h_i = gh[r*3*H + H + h], h_n = gh[r*3*H + 2*H + h];
    float hv  = hidden[r*H + h];
    float rg = 1.f / (1.f + expf(-(i_r + h_r)));
    float ig = 1.f / (1.f + expf(-(i_i + h_i)));
    float ng = tanhf(i_n + rg * h_n);
    hidden[r*H + h] = ng + ig * (hv - ng);
}

__device__ __forceinline__ float warp_sum(float v) {
#pragma unroll
    for (int off = 16; off > 0; off >>= 1) v += __shfl_down_sync(0xffffffffu, v, off);
    return v;
}

// attention pooling
__global__ void k_attn(const float* __restrict__ hidden, const int* __restrict__ mask,
                       const float* __restrict__ W_one, const float* __restrict__ b_one,
                       const float* __restrict__ q2, const float* __restrict__ w_three,
                       const float* __restrict__ W_tr, const float* __restrict__ b_tr,
                       float* __restrict__ a_vec, int* __restrict__ lenout) {
    int b = blockIdx.x, h = threadIdx.x;  // 128 threads
    __shared__ float ht_s[H], red[4], logits[NN], alpha[NN], c_s[2*H];
    int len = 0;
#pragma unroll
    for (int n = 0; n < NN; n++) len += mask[b*NN + n];
    ht_s[h] = hidden[(b*NN + len - 1)*H + h];
    __syncthreads();
    float q1 = b_one[h];
    for (int k = 0; k < H; k++) q1 += W_one[h*H + k] * ht_s[k];
    float w3 = w_three[h];
    for (int n = 0; n < NN; n++) {
        float v = 0.f;
        if (n < len) {
            float x = q1 + q2[(b*NN + n)*H + h];
            v = (1.f / (1.f + expf(-x))) * w3;
        }
        v = warp_sum(v);
        if ((h & 31) == 0) red[h >> 5] = v;
        __syncthreads();
        if (h == 0) logits[n] = red[0] + red[1] + red[2] + red[3];
        __syncthreads();
    }
    if (h == 0) {
        float m = -1e30f;
        for (int n = 0; n < len; n++) m = fmaxf(m, logits[n]);
        float s = 0.f;
        for (int n = 0; n < len; n++) { alpha[n] = expf(logits[n] - m); s += alpha[n]; }
        float inv = 1.f / s;
        for (int n = 0; n < len; n++) alpha[n] *= inv;
        lenout[b] = len;
    }
    __syncthreads();
    float ar = 0.f;
    for (int n = 0; n < len; n++) ar += alpha[n] * hidden[(b*NN + n)*H + h];
    c_s[h] = ar;
    c_s[H + h] = ht_s[h];
    __syncthreads();
    float av = b_tr[h];
    for (int k = 0; k < 2*H; k++) av += W_tr[h*2*H + k] * c_s[k];
    a_vec[b*H + h] = av;
}

// -------- Phase B: fused logits / softmax / weighted sum / bias-dot --------
// scores[b,v] = sum_n softmax_n(L[b,v,n]) * L[b,v,n] + a[b].emb[v+1]
// L[b,v,n] = emb[v+1].qt[b,n];  qt rows for masked n are exactly zero.
//
// v4: emb row lives in 128 REGISTERS per thread (loaded once per block via a
// small staged smem buffer) -> zero per-chunk e-LDS traffic. qt is stored
// TRANSPOSED in smem (qtsT[h][52]) so a CH=8 n-chunk at one h is 32 contiguous
// bytes = 2 broadcast LDS.128. FFMA2 accumulators are paired along n, so each
// u64 acc unpacks directly into two logits (no hsum).
#define CH 8
#define VT 128
#define NNP 52
__global__ void __launch_bounds__(128) k_scores(
        const float* __restrict__ qt, const float* __restrict__ a_vec,
        const float* __restrict__ emb, const int* __restrict__ lens,
        float* __restrict__ out) {
    extern __shared__ char sm_raw[];
    float4* ebuf = (float4*)sm_raw;                       // VT x 9 float4  (18.4KB)
    float*  qtsT = (float*)(sm_raw + VT*9*sizeof(float4)); // H x NNP floats (26.6KB)
    float4* a_s  = (float4*)(qtsT + H*NNP);                // 32 float4

    const int v0 = blockIdx.x * VT;
    const int tid = threadIdx.x;
    const float4 f4z = make_float4(0.f, 0.f, 0.f, 0.f);

    // ---- load this thread's emb row into registers, staged through smem ----
    float4 e[32];
    const float4* eg = (const float4*)emb;
#pragma unroll
    for (int p = 0; p < 4; p++) {
        if (p) __syncthreads();
#pragma unroll
        for (int l = 0; l < 8; l++) {
            int i = tid + 128*l;
            int r = i >> 3, c = i & 7;
            ebuf[r*9 + c] = (v0 + r < VM1) ? eg[(v0 + r + 1)*32 + p*8 + c] : f4z;
        }
        __syncthreads();
#pragma unroll
        for (int c = 0; c < 8; c++) e[p*8 + c] = ebuf[tid*9 + c];
    }

    const int v = v0 + tid;

    for (int bi = 0; bi < 2; bi++) {
        const int b = blockIdx.y * 2 + bi;
        __syncthreads();   // previous-b consumers done before restaging
        // stage qt transposed: thread tid == h; coalesced LDG, strided STS
        {
            const float* qb = qt + b*NN*H + tid;
            float* dst = qtsT + tid*NNP;
#pragma unroll
            for (int n = 0; n < NN; n++) dst[n] = qb[n*H];
        }
        if (tid < 32) a_s[tid] = ((const float4*)(a_vec + b*H))[tid];
        __syncthreads();

        const int len = lens[b];

        // adot = e . a   (pairs along h)
        u64 ad = 0ull;
        const ulonglong2* a2 = (const ulonglong2*)a_s;
#pragma unroll
        for (int h4 = 0; h4 < 32; h4++) {
            u64 elo = pack2(e[h4].x, e[h4].y);
            u64 ehi = pack2(e[h4].z, e[h4].w);
            ulonglong2 av = a2[h4];
            ffma2(ad, elo, av.x);
            ffma2(ad, ehi, av.y);
        }
        float adot = hsum2(ad);

        float expsum = 0.f, wsum = 0.f;
        for (int n0 = 0; n0 < len; n0 += CH) {
            u64 acc0 = 0ull, acc1 = 0ull, acc2v = 0ull, acc3 = 0ull;
            const float* qn = qtsT + n0;
#pragma unroll
            for (int h4 = 0; h4 < 32; h4++) {
                float4 ev = e[h4];
#pragma unroll
                for (int d = 0; d < 4; d++) {
                    float es = (d == 0) ? ev.x : (d == 1) ? ev.y : (d == 2) ? ev.z : ev.w;
                    u64 ed = pack2(es, es);
                    const ulonglong2* qp = (const ulonglong2*)(qn + (h4*4 + d)*NNP);
                    ulonglong2 qa = qp[0];   // n0..n0+3
                    ffma2(acc0, ed, qa.x);
                    ffma2(acc1, ed, qa.y);
                    ulonglong2 qb2 = qp[1];  // n0+4..n0+7
                    ffma2(acc2v, ed, qb2.x);
                    ffma2(acc3, ed, qb2.y);
                }
            }
            float lg[8];
            unpack2(acc0,  lg[0], lg[1]);
            unpack2(acc1,  lg[2], lg[3]);
            unpack2(acc2v, lg[4], lg[5]);
            unpack2(acc3,  lg[6], lg[7]);
#pragma unroll
            for (int j = 0; j < CH; j++) {
                if (n0 + j < len) {
                    float l = lg[j];
                    float el = __expf(l);   // |l| small by construction
                    expsum += el;
                    wsum   += l * el;
                }
            }
        }
        if (v < VM1) out[b*VM1 + v] = wsum / expsum + adot;
    }
}

// ---------------- launcher ----------------
extern "C" void kernel_launch(void* const* d_in, const int* in_sizes, int n_in,
                              void* d_out, int out_size) {
    const int*   items  = (const int*)  d_in[0];
    const float* A      = (const float*)d_in[1];
    const int*   mask   = (const int*)  d_in[2];
    const float* emb    = (const float*)d_in[3];
    const float* w_ih   = (const float*)d_in[4];
    const float* w_hh   = (const float*)d_in[5];
    const float* b_ih   = (const float*)d_in[6];
    const float* b_hh   = (const float*)d_in[7];
    const float* b_iah  = (const float*)d_in[8];
    const float* b_oah  = (const float*)d_in[9];
    const float* W_ein  = (const float*)d_in[10];
    const float* b_ein  = (const float*)d_in[11];
    const float* W_eout = (const float*)d_in[12];
    const float* b_eout = (const float*)d_in[13];
    const float* W_one  = (const float*)d_in[14];
    const float* b_one  = (const float*)d_in[15];
    const float* W_two  = (const float*)d_in[16];
    const float* b_two  = (const float*)d_in[17];
    const float* w_three= (const float*)d_in[18];
    const float* W_tr   = (const float*)d_in[19];
    const float* b_tr   = (const float*)d_in[20];
    const float* W_t    = (const float*)d_in[21];
    float* out = (float*)d_out;

    float *hidden, *ein, *eout, *inputs, *gi, *gh, *q2, *qt, *avec;
    int *lens;
    cudaGetSymbolAddress((void**)&hidden, g_hidden);
    cudaGetSymbolAddress((void**)&ein,    g_ein);
    cudaGetSymbolAddress((void**)&eout,   g_eout);
    cudaGetSymbolAddress((void**)&inputs, g_inputs);
    cudaGetSymbolAddress((void**)&gi,     g_gi);
    cudaGetSymbolAddress((void**)&gh,     g_gh);
    cudaGetSymbolAddress((void**)&q2,     g_q2);
    cudaGetSymbolAddress((void**)&qt,     g_qt);
    cudaGetSymbolAddress((void**)&avec,   g_avec);
    cudaGetSymbolAddress((void**)&lens,   g_len);

    const int R = B*NN;  // 800 rows
    const int RB = (R + 63) / 64;  // 13

    size_t smem_scores = (size_t)VT*9*sizeof(float4) + (size_t)H*NNP*sizeof(float)
                       + 32*sizeof(float4);

    k_embed<<<R, H>>>(items, emb, hidden);

    for (int step = 0; step < STEPS; step++) {
        k_einout<<<dim3(H/64, RB, 2), 256>>>(hidden, W_ein, b_ein, ein, W_eout, b_eout, eout);
        k_Amul<<<R, 256>>>(A, ein, eout, b_iah, b_oah, inputs);
        k_gates<<<dim3(3*H/64, RB, 2), 256>>>(inputs, hidden, w_ih, b_ih, gi, w_hh, b_hh, gh);
        k_gru<<<R, H>>>(gi, gh, hidden);
    }

    k_q2qt<<<dim3(H/64, RB, 2), 256>>>(hidden, W_two, b_two, q2, W_t, qt, mask);
    k_attn<<<B, H>>>(hidden, mask, W_one, b_one, q2, w_three, W_tr, b_tr, avec, lens);

    k_scores<<<dim3((VM1 + VT - 1)/VT, B/2), 128, smem_scores>>>(qt, avec, emb, lens, out);
}

// round 11
// speedup vs baseline: 1.3380x; 1.3380x over previous
#include <cuda_runtime.h>
#include <cuda_bf16.h>
#include <math.h>

// Problem constants
#define B 16
#define NN 50
#define H 128
#define V 40000
#define STEPS 2
#define VM1 39999   // output vocab (emb[1:])

typedef unsigned long long u64;

// packed 2x fp32 FMA (Blackwell f32x2: 2 MACs per issue slot)
__device__ __forceinline__ void ffma2(u64& d, u64 a, u64 b) {
    asm("fma.rn.f32x2 %0, %1, %2, %0;" : "+l"(d) : "l"(a), "l"(b));
}
__device__ __forceinline__ float hsum2(u64 p) {
    float lo = __uint_as_float((unsigned)(p & 0xffffffffu));
    float hi = __uint_as_float((unsigned)(p >> 32));
    return lo + hi;
}

// ---------------- scratch (no allocation allowed) ----------------
__device__ __align__(16) float g_hidden[B*NN*H];
__device__ __align__(16) float g_ein[B*NN*H];
__device__ __align__(16) float g_eout[B*NN*H];
__device__ __align__(16) float g_inputs[B*NN*2*H];
__device__ __align__(16) float g_gi[B*NN*3*H];
__device__ __align__(16) float g_gh[B*NN*3*H];
__device__ __align__(16) float g_q2[B*NN*H];
__device__ __align__(16) float g_qt[B*NN*H];
__device__ __align__(16) float g_avec[B*H];
__device__ int g_len[B];

// ---------------- kernels ----------------

// hidden[r][h] = emb[items[r]][h]
__global__ void k_embed(const int* __restrict__ items, const float* __restrict__ emb,
                        float* __restrict__ hidden) {
    int r = blockIdx.x, h = threadIdx.x;
    hidden[r*H + h] = emb[items[r]*H + h];
}

// Shared GEMM body: C[M x N] = X[M x K] @ W[N x K]^T + bias
// (tiled 64x64, 256 threads, 4x4 microtile). Optional row mask applied to X.
// (R8 version — the register-prefetch variant regressed and was reverted.)
__device__ __forceinline__ void gemm_body(const float* __restrict__ X, const float* __restrict__ W,
                                          const float* __restrict__ bias, float* __restrict__ C,
                                          int M, int N, int K, const int* __restrict__ mask) {
    __shared__ float Xs[64][17];
    __shared__ float Ws[64][17];
    const int i0 = blockIdx.y * 64;
    const int j0 = blockIdx.x * 64;
    const int tx = threadIdx.x & 15;      // col group
    const int ty = threadIdx.x >> 4;      // row group
    float acc[4][4];
#pragma unroll
    for (int a = 0; a < 4; a++)
#pragma unroll
        for (int b = 0; b < 4; b++) acc[a][b] = 0.f;

    for (int k0 = 0; k0 < K; k0 += 16) {
#pragma unroll
        for (int l = 0; l < 4; l++) {
            int idx = l*256 + threadIdx.x;
            int i = idx >> 4, k = idx & 15;
            int gi = i0 + i;
            float xv = 0.f;
            if (gi < M) {
                xv = X[gi*K + k0 + k];
                if (mask && !mask[gi]) xv = 0.f;
            }
            Xs[i][k] = xv;
            int gj = j0 + i;
            Ws[i][k] = (gj < N) ? W[gj*K + k0 + k] : 0.f;
        }
        __syncthreads();
#pragma unroll
        for (int k = 0; k < 16; k++) {
            float xr[4], wr[4];
#pragma unroll
            for (int a = 0; a < 4; a++) { xr[a] = Xs[ty*4+a][k]; wr[a] = Ws[tx*4+a][k]; }
#pragma unroll
            for (int a = 0; a < 4; a++)
#pragma unroll
                for (int b = 0; b < 4; b++) acc[a][b] += xr[a] * wr[b];
        }
        __syncthreads();
    }
#pragma unroll
    for (int a = 0; a < 4; a++) {
        int i = i0 + ty*4 + a;
        if (i >= M) continue;
#pragma unroll
        for (int b = 0; b < 4; b++) {
            int j = j0 + tx*4 + b;
            float v = acc[a][b];
            if (bias) v += bias[j];
            C[i*N + j] = v;
        }
    }
}

// fused ein/eout GEMMs (blockIdx.z selects)
__global__ void k_einout(const float* hidden, const float* W_ein, const float* b_ein, float* ein,
                         const float* W_eout, const float* b_eout, float* eout) {
    if (blockIdx.z == 0) gemm_body(hidden, W_ein,  b_ein,  ein,  B*NN, H, H, nullptr);
    else                 gemm_body(hidden, W_eout, b_eout, eout, B*NN, H, H, nullptr);
}

// fused gate GEMMs
__global__ void k_gates(const float* inputs, const float* hidden,
                        const float* w_ih, const float* b_ih, float* gi_,
                        const float* w_hh, const float* b_hh, float* gh_) {
    if (blockIdx.z == 0) gemm_body(inputs, w_ih, b_ih, gi_, B*NN, 3*H, 2*H, nullptr);
    else                 gemm_body(hidden, w_hh, b_hh, gh_, B*NN, 3*H, H,   nullptr);
}

// fused q2/qt GEMMs
__global__ void k_q2qt(const float* hidden, const float* W_two, const float* b_two, float* q2,
                       const float* W_t, float* qt, const int* mask) {
    if (blockIdx.z == 0) gemm_body(hidden, W_two, b_two,   q2, B*NN, H, H, nullptr);
    else                 gemm_body(hidden, W_t,   nullptr, qt, B*NN, H, H, mask);
}

// inputs[r] = [A_in[r] @ ein_b + b_iah , A_out[r] @ eout_b + b_oah]
__global__ void k_Amul(const float* __restrict__ A, const float* __restrict__ ein,
                       const float* __restrict__ eout, const float* __restrict__ b_iah,
                       const float* __restrict__ b_oah, float* __restrict__ inputs) {
    int r = blockIdx.x, b = r / NN;
    int tid = threadIdx.x;
    int half = tid >> 7, h = tid & 127;
    __shared__ float Ar[2*NN];
    __shared__ float red[2*H];
    if (tid < 2*NN) Ar[tid] = A[r*2*NN + tid];
    __syncthreads();
    const float* eb = ein  + b*NN*H + h;
    const float* ob = eout + b*NN*H + h;
    float ain = 0.f, aout = 0.f;
    int m0 = half * 25;
#pragma unroll
    for (int m = 0; m < 25; m++) {
        ain  += Ar[m0 + m]      * eb[(m0 + m)*H];
        aout += Ar[NN + m0 + m] * ob[(m0 + m)*H];
    }
    if (half) { red[h] = ain; red[H + h] = aout; }
    __syncthreads();
    if (!half) {
        inputs[r*2*H + h]     = ain  + red[h]     + b_iah[h];
        inputs[r*2*H + H + h] = aout + red[H + h] + b_oah[h];
    }
}

// GRU gate update (in-place on hidden)
__global__ void k_gru(const float* __restrict__ gi, const float* __restrict__ gh,
                      float* __restrict__ hidden) {
    int r = blockIdx.x, h = threadIdx.x;
    float i_r = gi[r*3*H + h], i_i = gi[r*3*H + H + h], i_n = gi[r*3*H + 2*H + h];
    float h_r = gh[r*3*H + h], h_i = gh[r*3*H + H + h], h_n = gh[r*3*H + 2*H + h];
    float hv  = hidden[r*H + h];
    float rg = 1.f / (1.f + expf(-(i_r + h_r)));
    float ig = 1.f / (1.f + expf(-(i_i + h_i)));
    float ng = tanhf(i_n + rg * h_n);
    hidden[r*H + h] = ng + ig * (hv - ng);
}

__device__ __forceinline__ float warp_sum(float v) {
#pragma unroll
    for (int off = 16; off > 0; off >>= 1) v += __shfl_down_sync(0xffffffffu, v, off);
    return v;
}

// attention pooling
__global__ void k_attn(const float* __restrict__ hidden, const int* __restrict__ mask,
                       const float* __restrict__ W_one, const float* __restrict__ b_one,
                       const float* __restrict__ q2, const float* __restrict__ w_three,
                       const float* __restrict__ W_tr, const float* __restrict__ b_tr,
                       float* __restrict__ a_vec, int* __restrict__ lenout) {
    int b = blockIdx.x, h = threadIdx.x;  // 128 threads
    __shared__ float ht_s[H], red[4], logits[NN], alpha[NN], c_s[2*H];
    int len = 0;
#pragma unroll
    for (int n = 0; n < NN; n++) len += mask[b*NN + n];
    ht_s[h] = hidden[(b*NN + len - 1)*H + h];
    __syncthreads();
    float q1 = b_one[h];
    for (int k = 0; k < H; k++) q1 += W_one[h*H + k] * ht_s[k];
    float w3 = w_three[h];
    for (int n = 0; n < NN; n++) {
        float v = 0.f;
        if (n < len) {
            float x = q1 + q2[(b*NN + n)*H + h];
            v = (1.f / (1.f + expf(-x))) * w3;
        }
        v = warp_sum(v);
        if ((h & 31) == 0) red[h >> 5] = v;
        __syncthreads();
        if (h == 0) logits[n] = red[0] + red[1] + red[2] + red[3];
        __syncthreads();
    }
    if (h == 0) {
        float m = -1e30f;
        for (int n = 0; n < len; n++) m = fmaxf(m, logits[n]);
        float s = 0.f;
        for (int n = 0; n < len; n++) { alpha[n] = expf(logits[n] - m); s += alpha[n]; }
        float inv = 1.f / s;
        for (int n = 0; n < len; n++) alpha[n] *= inv;
        lenout[b] = len;
    }
    __syncthreads();
    float ar = 0.f;
    for (int n = 0; n < len; n++) ar += alpha[n] * hidden[(b*NN + n)*H + h];
    c_s[h] = ar;
    c_s[H + h] = ht_s[h];
    __syncthreads();
    float av = b_tr[h];
    for (int k = 0; k < 2*H; k++) av += W_tr[h*2*H + k] * c_s[k];
    a_vec[b*H + h] = av;
}

// -------- Phase B: fused logits / softmax / weighted sum / bias-dot --------
// scores[b,v] = sum_n softmax_n(L[b,v,n]) * L[b,v,n] + a[b].emb[v+1]
// L[b,v,n] = emb[v+1].qt[b,n];  qt rows for masked n are exactly zero.
//
// v5 = v3 structure + register-blocking over v: each thread computes TWO vocab
// rows (tid and tid+128, VT=256/block). The 10 broadcast q-LDS per h-iter are
// amortized over 2x the FFMA2 work -> kernel flips from crossbar-bound to
// fma-bound (~1.4x). smem 158KB -> 1 block/SM; 20 independent accumulators
// give the ILP to hide LDS latency at 1 warp/SMSP.
#define CH 10
#define VT 256
__global__ void __launch_bounds__(128) k_scores(
        const float* __restrict__ qt, const float* __restrict__ a_vec,
        const float* __restrict__ emb, const int* __restrict__ lens,
        float* __restrict__ out) {
    extern __shared__ float4 sm[];
    float4* embs = sm;                 // VT rows x 33 float4 (padded, conflict-free)
    float4* qts  = sm + VT*33;         // NN x 32
    float4* a_s  = qts + NN*32;        // 32

    const int v0 = blockIdx.x * VT;
    const int tid = threadIdx.x;
    const float4 f4z = make_float4(0.f, 0.f, 0.f, 0.f);

    // stage emb tile once, coalesced (zero-fill OOB rows)
    const float4* eg = (const float4*)emb;
    for (int i = tid; i < VT*32; i += 128) {
        int r = i >> 5, c = i & 31;
        embs[r*33 + c] = (v0 + r < VM1) ? eg[(v0 + r + 1)*32 + c] : f4z;
    }

    const int va = v0 + tid;
    const int vb = v0 + 128 + tid;
    const ulonglong2* erowA = reinterpret_cast<const ulonglong2*>(embs + tid*33);
    const ulonglong2* erowB = reinterpret_cast<const ulonglong2*>(embs + (tid + 128)*33);
    const ulonglong2* a2    = reinterpret_cast<const ulonglong2*>(a_s);

    for (int bi = 0; bi < 2; bi++) {
        const int b = blockIdx.y * 2 + bi;
        __syncthreads();   // previous-b consumers done before restaging
        const float4* qb4 = (const float4*)(qt + b*NN*H);
        for (int i = tid; i < NN*32; i += 128) qts[i] = qb4[i];
        if (tid < 32) a_s[tid] = ((const float4*)(a_vec + b*H))[tid];
        __syncthreads();

        const int len = lens[b];
        u64 adA = 0ull, adB = 0ull;
        float expsA = 0.f, wsA = 0.f, expsB = 0.f, wsB = 0.f;

        for (int n0 = 0; n0 < len; n0 += CH) {
            u64 accA[CH], accB[CH];
#pragma unroll
            for (int j = 0; j < CH; j++) { accA[j] = 0ull; accB[j] = 0ull; }
            const ulonglong2* qbase = reinterpret_cast<const ulonglong2*>(qts + n0*32);
            if (n0 == 0) {
#pragma unroll 8
                for (int h = 0; h < 32; h++) {
                    ulonglong2 eA = erowA[h];
                    ulonglong2 eB = erowB[h];
                    ulonglong2 av = a2[h];
                    ffma2(adA, eA.x, av.x); ffma2(adA, eA.y, av.y);
                    ffma2(adB, eB.x, av.x); ffma2(adB, eB.y, av.y);
#pragma unroll
                    for (int j = 0; j < CH; j++) {
                        ulonglong2 q = qbase[j*32 + h];
                        ffma2(accA[j], eA.x, q.x); ffma2(accA[j], eA.y, q.y);
                        ffma2(accB[j], eB.x, q.x); ffma2(accB[j], eB.y, q.y);
                    }
                }
            } else {
#pragma unroll 8
                for (int h = 0; h < 32; h++) {
                    ulonglong2 eA = erowA[h];
                    ulonglong2 eB = erowB[h];
#pragma unroll
                    for (int j = 0; j < CH; j++) {
                        ulonglong2 q = qbase[j*32 + h];
                        ffma2(accA[j], eA.x, q.x); ffma2(accA[j], eA.y, q.y);
                        ffma2(accB[j], eB.x, q.x); ffma2(accB[j], eB.y, q.y);
                    }
                }
            }
#pragma unroll
            for (int j = 0; j < CH; j++) {
                if (n0 + j < len) {
                    float lA = hsum2(accA[j]);
                    float eA = __expf(lA);   // |l| small by construction
                    expsA += eA; wsA += lA * eA;
                    float lB = hsum2(accB[j]);
                    float eB = __expf(lB);
                    expsB += eB; wsB += lB * eB;
                }
            }
        }
        if (va < VM1) out[b*VM1 + va] = wsA / expsA + hsum2(adA);
        if (vb < VM1) out[b*VM1 + vb] = wsB / expsB + hsum2(adB);
    }
}

// ---------------- launcher ----------------
extern "C" void kernel_launch(void* const* d_in, const int* in_sizes, int n_in,
                              void* d_out, int out_size) {
    const int*   items  = (const int*)  d_in[0];
    const float* A      = (const float*)d_in[1];
    const int*   mask   = (const int*)  d_in[2];
    const float* emb    = (const float*)d_in[3];
    const float* w_ih   = (const float*)d_in[4];
    const float* w_hh   = (const float*)d_in[5];
    const float* b_ih   = (const float*)d_in[6];
    const float* b_hh   = (const float*)d_in[7];
    const float* b_iah  = (const float*)d_in[8];
    const float* b_oah  = (const float*)d_in[9];
    const float* W_ein  = (const float*)d_in[10];
    const float* b_ein  = (const float*)d_in[11];
    const float* W_eout = (const float*)d_in[12];
    const float* b_eout = (const float*)d_in[13];
    const float* W_one  = (const float*)d_in[14];
    const float* b_one  = (const float*)d_in[15];
    const float* W_two  = (const float*)d_in[16];
    const float* b_two  = (const float*)d_in[17];
    const float* w_three= (const float*)d_in[18];
    const float* W_tr   = (const float*)d_in[19];
    const float* b_tr   = (const float*)d_in[20];
    const float* W_t    = (const float*)d_in[21];
    float* out = (float*)d_out;

    float *hidden, *ein, *eout, *inputs, *gi, *gh, *q2, *qt, *avec;
    int *lens;
    cudaGetSymbolAddress((void**)&hidden, g_hidden);
    cudaGetSymbolAddress((void**)&ein,    g_ein);
    cudaGetSymbolAddress((void**)&eout,   g_eout);
    cudaGetSymbolAddress((void**)&inputs, g_inputs);
    cudaGetSymbolAddress((void**)&gi,     g_gi);
    cudaGetSymbolAddress((void**)&gh,     g_gh);
    cudaGetSymbolAddress((void**)&q2,     g_q2);
    cudaGetSymbolAddress((void**)&qt,     g_qt);
    cudaGetSymbolAddress((void**)&avec,   g_avec);
    cudaGetSymbolAddress((void**)&lens,   g_len);

    const int R = B*NN;  // 800 rows
    const int RB = (R + 63) / 64;  // 13

    size_t smem_scores = (size_t)(VT*33 + NN*32 + 32) * sizeof(float4);
    cudaFuncSetAttribute(k_scores, cudaFuncAttributeMaxDynamicSharedMemorySize,
                         (int)smem_scores);

    k_embed<<<R, H>>>(items, emb, hidden);

    for (int step = 0; step < STEPS; step++) {
        k_einout<<<dim3(H/64, RB, 2), 256>>>(hidden, W_ein, b_ein, ein, W_eout, b_eout, eout);
        k_Amul<<<R, 256>>>(A, ein, eout, b_iah, b_oah, inputs);
        k_gates<<<dim3(3*H/64, RB, 2), 256>>>(inputs, hidden, w_ih, b_ih, gi, w_hh, b_hh, gh);
        k_gru<<<R, H>>>(gi, gh, hidden);
    }

    k_q2qt<<<dim3(H/64, RB, 2), 256>>>(hidden, W_two, b_two, q2, W_t, qt, mask);
    k_attn<<<B, H>>>(hidden, mask, W_one, b_one, q2, w_three, W_tr, b_tr, avec, lens);

    k_scores<<<dim3((VM1 + VT - 1)/VT, B/2), 128, smem_scores>>>(qt, avec, emb, lens, out);
}